// round 14
// baseline (speedup 1.0000x reference)
#include <cuda_runtime.h>
#include <math.h>

#define BS 4
#define LEN 2048
#define CIN 32
#define COUT 32
#define HIDDIM 64
#define KTAP 8
#define PADL 7
#define NPOS (BS * LEN)
#define RDIM (CIN * HIDDIM)      // 2048
#define EPSV 1e-5f
#define NWA 8                     // K1: positions per block
#define NPB 32                    // K2: positions per block
#define NBLK2 (NPOS / NPB)        // 256

typedef unsigned long long u64;

// ---- global scratch (device globals: allocation-free) ----
__device__ u64    g_M[(size_t)NPOS * 1024];   // [p][q(32)][c(32)]: (M[c][2q],M[c][2q+1])
__device__ float  g_fsum[NPOS * CIN];
__device__ int    g_pany[NPOS];
__device__ double g_stats[2 * COUT];
__device__ int    g_sync;

// ---- register-pure packed helpers ----
#define FMA2(d, a, b, c) \
    asm("fma.rn.f32x2 %0, %1, %2, %3;" : "=l"(d) : "l"(a), "l"(b), "l"(c))

__device__ __forceinline__ u64 pack2(float x, float y) {
    u64 d; asm("mov.b64 %0, {%1, %2};" : "=l"(d) : "f"(x), "f"(y)); return d;
}
__device__ __forceinline__ u64 packdup(float x) {
    u64 d; asm("mov.b64 %0, {%1, %1};" : "=l"(d) : "f"(x)); return d;
}
__device__ __forceinline__ void unpack2(u64 v, float& x, float& y) {
    asm("mov.b64 {%0, %1}, %2;" : "=f"(x), "=f"(y) : "l"(v));
}

// mask dtype hedge (byte 1 nonzero <=> 1-byte storage; else 4-byte words)
__device__ __forceinline__ bool mask_at(const void* m, int idx, bool byte_mode) {
    if (byte_mode) return ((const unsigned char*)m)[idx] != 0;
    return ((const unsigned int*)m)[idx] != 0u;
}

// ===========================================================================
// K1: phase A — build M rows (teu conflict-fixed layout)
// ===========================================================================
__global__ __launch_bounds__(256, 3)
void k1(const float* __restrict__ times,
        const float* __restrict__ features,
        const void*  __restrict__ mask,
        const float* __restrict__ W1,
        const float* __restrict__ b1) {
    __shared__ float W1s[CIN * HIDDIM];
    __shared__ float b1s[HIDDIM];
    __shared__ float teu[NWA][4][CIN][2];   // [kpair][i][e]: 2-way STS only
    __shared__ float hb[NWA][KTAP][HIDDIM];

    int tid  = threadIdx.x;
    int wid  = tid >> 5;
    int lane = tid & 31;

    for (int i = tid; i < CIN * HIDDIM; i += 256) W1s[i] = W1[i];
    if (tid < HIDDIM) b1s[tid] = b1[tid];
    __syncthreads();

    int p = blockIdx.x * NWA + wid;
    int b = p >> 11;
    int t = p & (LEN - 1);

    bool byte_mode = ((const unsigned char*)mask)[1] != 0;
    bool mask_t = mask_at(mask, p, byte_mode);
    float t_here = times[p];

    unsigned vmask = 0;
#pragma unroll
    for (int k = 0; k < KTAP; k++) {
        int idx = t - PADL + k;
        bool dm = mask_t && (idx >= 0);
        if (dm) dm = mask_at(mask, b * LEN + idx, byte_mode);
        if (dm) vmask |= (1u << k);
    }
    bool any = (vmask != 0);
    float fsum = 0.0f;

    if (any) {
        // --- te for all taps (lane = channel i) ---
        float inv_pos = __expf(-(float)(lane >> 1) * (9.210340371976184f / 16.0f));
        float phase   = (lane & 1) ? 1.5707963267948966f : 0.0f;
        float fk[KTAP];
#pragma unroll
        for (int k = 0; k < KTAP; k++) {
            int idx = t - PADL + k;
            float te = 0.0f;
            fk[k] = 0.0f;
            if ((vmask >> k) & 1) {
                float dt = t_here - times[b * LEN + idx];
                te = __sinf(dt * inv_pos + phase);
                fk[k] = features[(size_t)(b * LEN + idx) * CIN + lane];
            }
            teu[wid][k >> 1][lane][k & 1] = te;
            fsum += fk[k];
        }
        __syncwarp();

        // --- h for all taps, i-outer (lane = j; also j+32) ---
        u64 hh[4][2];
#pragma unroll
        for (int k2 = 0; k2 < 4; k2++) {
            hh[k2][0] = packdup(b1s[lane]);
            hh[k2][1] = packdup(b1s[lane + 32]);
        }
#pragma unroll
        for (int i = 0; i < CIN; i++) {
            u64 w0 = packdup(W1s[i * HIDDIM + lane]);
            u64 w1 = packdup(W1s[i * HIDDIM + lane + 32]);
#pragma unroll
            for (int k2 = 0; k2 < 4; k2++) {
                u64 tp = *(const u64*)&teu[wid][k2][i][0];   // broadcast LDS.64
                FMA2(hh[k2][0], tp, w0, hh[k2][0]);
                FMA2(hh[k2][1], tp, w1, hh[k2][1]);
            }
        }
#pragma unroll
        for (int k2 = 0; k2 < 4; k2++) {
            float a0, c0, a1, c1;
            unpack2(hh[k2][0], a0, c0);
            unpack2(hh[k2][1], a1, c1);
            hb[wid][2 * k2][lane]          = fmaxf(a0, 0.0f);
            hb[wid][2 * k2 + 1][lane]      = fmaxf(c0, 0.0f);
            hb[wid][2 * k2][lane + 32]     = fmaxf(a1, 0.0f);
            hb[wid][2 * k2 + 1][lane + 32] = fmaxf(c1, 0.0f);
        }
        __syncwarp();

        // --- M update (lane = channel), two j-half passes ---
#pragma unroll
        for (int half = 0; half < 2; half++) {
            u64 Macc[16];
#pragma unroll
            for (int q = 0; q < 16; q++) Macc[q] = 0ull;
#pragma unroll
            for (int k = 0; k < KTAP; k++) {
                if (!((vmask >> k) & 1)) continue;     // warp-uniform
                u64 f2 = packdup(fk[k]);
                const ulonglong2* hp2 =
                    (const ulonglong2*)&hb[wid][k][half * 32];
#pragma unroll
                for (int q2 = 0; q2 < 8; q2++) {
                    ulonglong2 hp = hp2[q2];           // broadcast LDS.128
                    FMA2(Macc[2 * q2],     f2, hp.x, Macc[2 * q2]);
                    FMA2(Macc[2 * q2 + 1], f2, hp.y, Macc[2 * q2 + 1]);
                }
            }
#pragma unroll
            for (int q = 0; q < 16; q++)
                g_M[((size_t)p * 32 + half * 16 + q) * 32 + lane] = Macc[q];
        }
    }
    g_fsum[p * CIN + lane] = fsum;
    if (lane == 0) g_pany[p] = any ? 1 : 0;
}

// ===========================================================================
// K2: tiled GEMM C[32x32] per block; K=2048 in 32 double-buffered chunks.
//     Warp owns 4 positions end-to-end (no cross-warp reduction).
// ===========================================================================
struct SmemK2 {
    u64   At[2][NPB][34];         // A chunk tiles (pitch 34 u64)   17.4KB
    u64   Wt[2][32][32];          // W2 pair tiles                  16KB
    float b2s[CIN * COUT];        // 4KB
    float wsk[CIN * COUT];        // 4KB
    float bsk[COUT];
    float fs[NPB][CIN];           // 4KB
    float ff[NPB][CIN];           // 4KB
    float ssum[COUT], ssq[COUT];
    int   pf[NPB];
};                                // ~50.7KB

__global__ __launch_bounds__(256)
void k2(const float* __restrict__ features,
        const float* __restrict__ W2,
        const float* __restrict__ b2,
        const float* __restrict__ Wskip,
        const float* __restrict__ bskip,
        float* __restrict__ out) {
    extern __shared__ char smem_raw[];
    SmemK2* s = (SmemK2*)smem_raw;

    int tid  = threadIdx.x;
    int wid  = tid >> 5;
    int lane = tid & 31;
    int p0   = blockIdx.x * NPB;

    for (int i = tid; i < CIN * COUT; i += 256) {
        s->b2s[i] = b2[i];
        s->wsk[i] = Wskip[i];
    }
    for (int i = tid; i < NPB * CIN; i += 256) {
        int pos = i >> 5, c = i & 31;
        s->fs[pos][c] = g_fsum[(p0 + pos) * CIN + c];
        s->ff[pos][c] = features[(size_t)(p0 + pos) * CIN + c];
    }
    if (tid < COUT) { s->bsk[tid] = bskip[tid]; s->ssum[tid] = 0.0f; s->ssq[tid] = 0.0f; }
    if (tid < NPB)  s->pf[tid] = g_pany[p0 + tid];

    // staging thread maps
    int pos_s = tid >> 3, e_s = tid & 7;     // A: 4 u64 per thread
    int og = tid & 31, cg = tid >> 5;        // W: 4 c-rows per thread

    // stage chunk 0 into buf 0
    {
        const ulonglong2* asrc =
            (const ulonglong2*)&g_M[((size_t)(p0 + pos_s)) * 1024 + 4 * e_s];
        ulonglong2 a0 = asrc[0], a1 = asrc[1];
        ulonglong2* adst = (ulonglong2*)&s->At[0][pos_s][4 * e_s];
        adst[0] = a0; adst[1] = a1;
#pragma unroll
        for (int j = 0; j < 4; j++) {
            int c = cg * 4 + j;
            float f0 = W2[0 * 1024 + c * 32 + og];
            float f1 = W2[1 * 1024 + c * 32 + og];
            s->Wt[0][c][og] = pack2(f0, f1);
        }
    }
    __syncthreads();

    // per-warp position flags (bits 0..3)
    unsigned pfm = __ballot_sync(0xffffffffu,
                                 (lane < 4) ? (s->pf[wid * 4 + lane] != 0) : 0);

    u64 acc[4];
#pragma unroll
    for (int q = 0; q < 4; q++) acc[q] = 0ull;

    for (int k = 0; k < 32; k++) {
        int buf = k & 1;

        // prefetch chunk k+1 into registers (latency hidden by compute)
        ulonglong2 pa0, pa1;
        float pw0[4], pw1[4];
        if (k < 31) {
            const ulonglong2* asrc = (const ulonglong2*)
                &g_M[((size_t)(p0 + pos_s)) * 1024 + (k + 1) * 32 + 4 * e_s];
            pa0 = asrc[0]; pa1 = asrc[1];
#pragma unroll
            for (int j = 0; j < 4; j++) {
                int c = cg * 4 + j;
                pw0[j] = W2[(2 * (k + 1)) * 1024 + c * 32 + og];
                pw1[j] = W2[(2 * (k + 1) + 1) * 1024 + c * 32 + og];
            }
        }

        // compute chunk k: c in 4 windows of 8
#pragma unroll
        for (int h = 0; h < 4; h++) {
            u64 wreg[8];
#pragma unroll
            for (int q = 0; q < 8; q++) wreg[q] = s->Wt[buf][h * 8 + q][lane];
#pragma unroll
            for (int pj = 0; pj < 4; pj++) {
                if (!((pfm >> pj) & 1)) continue;      // warp-uniform
                const ulonglong2* ap =
                    (const ulonglong2*)&s->At[buf][wid * 4 + pj][h * 8];
#pragma unroll
                for (int q2 = 0; q2 < 4; q2++) {
                    ulonglong2 a = ap[q2];             // broadcast LDS.128
                    FMA2(acc[pj], a.x, wreg[2 * q2],     acc[pj]);
                    FMA2(acc[pj], a.y, wreg[2 * q2 + 1], acc[pj]);
                }
            }
        }

        if (k < 31) {
            int nbuf = buf ^ 1;
            ulonglong2* adst = (ulonglong2*)&s->At[nbuf][pos_s][4 * e_s];
            adst[0] = pa0; adst[1] = pa1;
#pragma unroll
            for (int j = 0; j < 4; j++)
                s->Wt[nbuf][cg * 4 + j][og] = pack2(pw0[j], pw1[j]);
        }
        __syncthreads();
    }

    // ---- epilogue: each warp finalizes its 4 positions ----
    float osum = 0.0f, osq = 0.0f;
#pragma unroll
    for (int pj = 0; pj < 4; pj++) {
        int pp = wid * 4 + pj;
        float lo, hi;
        unpack2(acc[pj], lo, hi);
        float o = ((pfm >> pj) & 1) ? (lo + hi) : 0.0f;

        const float4* fs4 = (const float4*)&s->fs[pp][0];
        const float4* ff4 = (const float4*)&s->ff[pp][0];
#pragma unroll
        for (int q = 0; q < CIN / 4; q++) {
            float4 a  = fs4[q];
            float4 cf = ff4[q];
            o += a.x  * s->b2s[(q * 4 + 0) * 32 + lane];
            o += a.y  * s->b2s[(q * 4 + 1) * 32 + lane];
            o += a.z  * s->b2s[(q * 4 + 2) * 32 + lane];
            o += a.w  * s->b2s[(q * 4 + 3) * 32 + lane];
            o += cf.x * s->wsk[(q * 4 + 0) * 32 + lane];
            o += cf.y * s->wsk[(q * 4 + 1) * 32 + lane];
            o += cf.z * s->wsk[(q * 4 + 2) * 32 + lane];
            o += cf.w * s->wsk[(q * 4 + 3) * 32 + lane];
        }
        o += s->bsk[lane];

        out[(size_t)(p0 + pp) * COUT + lane] = o;
        osum += o;
        osq  += o * o;
    }

    atomicAdd(&s->ssum[lane], osum);
    atomicAdd(&s->ssq[lane], osq);
    __syncthreads();
    if (tid < COUT)           atomicAdd(&g_stats[tid], (double)s->ssum[tid]);
    else if (tid < 2 * COUT)  atomicAdd(&g_stats[tid], (double)s->ssq[tid - COUT]);
}

// ---------------------------------------------------------------------------
// K3: LayerNorm finalize; last-arriving block re-zeros g_stats for replay
// ---------------------------------------------------------------------------
__global__ void k3(float* __restrict__ out,
                   const float* __restrict__ gamma,
                   const float* __restrict__ beta) {
    __shared__ float sc[COUT], sb[COUT];
    int tid = threadIdx.x;
    if (tid < COUT) {
        double n = (double)NPOS;
        double mean = g_stats[tid] / n;
        double var  = g_stats[COUT + tid] / n - mean * mean;
        float rstd = rsqrtf((float)var + EPSV);
        float g = gamma[tid] * rstd;
        sc[tid] = g;
        sb[tid] = beta[tid] - g * (float)mean;
    }
    __syncthreads();

    int e4 = blockIdx.x * blockDim.x + tid;
    if (e4 < NPOS * COUT / 4) {
        int o0 = (e4 * 4) & (COUT - 1);
        float4 v = ((const float4*)out)[e4];
        v.x = v.x * sc[o0]     + sb[o0];
        v.y = v.y * sc[o0 + 1] + sb[o0 + 1];
        v.z = v.z * sc[o0 + 2] + sb[o0 + 2];
        v.w = v.w * sc[o0 + 3] + sb[o0 + 3];
        ((float4*)out)[e4] = v;
    }
    __syncthreads();
    if (tid == 0) {
        __threadfence();
        int old = atomicAdd(&g_sync, 1);
        if (old == (int)gridDim.x - 1) {
            for (int i = 0; i < 2 * COUT; i++) g_stats[i] = 0.0;
            __threadfence();
            g_sync = 0;
        }
    }
}

// ---------------------------------------------------------------------------
extern "C" void kernel_launch(void* const* d_in, const int* in_sizes, int n_in,
                              void* d_out, int out_size) {
    const float* times    = (const float*)d_in[0];
    const float* features = (const float*)d_in[1];
    const void*  mask     = d_in[2];
    const float* W1    = (const float*)d_in[3];
    const float* b1    = (const float*)d_in[4];
    const float* W2    = (const float*)d_in[5];
    const float* b2    = (const float*)d_in[6];
    const float* Wskip = (const float*)d_in[7];
    const float* bskip = (const float*)d_in[8];
    const float* gamma = (const float*)d_in[9];
    const float* beta  = (const float*)d_in[10];
    float* out = (float*)d_out;

    cudaFuncSetAttribute(k2, cudaFuncAttributeMaxDynamicSharedMemorySize,
                         (int)sizeof(SmemK2));

    k1<<<NPOS / NWA, 256>>>(times, features, mask, W1, b1);
    k2<<<NBLK2, 256, sizeof(SmemK2)>>>(features, W2, b2, Wskip, bskip, out);
    k3<<<(NPOS * COUT / 4 + 255) / 256, 256>>>(out, gamma, beta);
}

// round 16
// speedup vs baseline: 2.1450x; 2.1450x over previous
#include <cuda_runtime.h>
#include <cuda_bf16.h>
#include <math.h>

#define BS 4
#define LEN 2048
#define CIN 32
#define COUT 32
#define HIDDIM 64
#define KTAP 8
#define PADL 7
#define NPOS (BS * LEN)
#define RDIM 2048
#define EPSV 1e-5f
#define NWA 8
#define K1BLK (NPOS / NWA)        // 1024
#define K2POS 64                   // positions per k2 block
#define K2BLK (NPOS / K2POS)       // 128

typedef unsigned long long u64;
typedef unsigned int u32;

// ---- global scratch ----
__device__ float  g_Mf[(size_t)NPOS * RDIM];   // [p][r], r = j*32+c
__device__ u32    g_Bh[1024 * 32];             // [kp][o] bf16x2 (W'[2kp], W'[2kp+1])
__device__ u32    g_Bl[1024 * 32];
__device__ float  g_fsum[NPOS * CIN];
__device__ double g_stats[2 * COUT];
__device__ int    g_sync;

// ---- packed fp32x2 helpers (k1) ----
#define FMA2(d, a, b, c) \
    asm("fma.rn.f32x2 %0, %1, %2, %3;" : "=l"(d) : "l"(a), "l"(b), "l"(c))
__device__ __forceinline__ u64 packdup(float x) {
    u64 d; asm("mov.b64 %0, {%1, %1};" : "=l"(d) : "f"(x)); return d;
}
__device__ __forceinline__ void unpack2(u64 v, float& x, float& y) {
    asm("mov.b64 {%0, %1}, %2;" : "=f"(x), "=f"(y) : "l"(v));
}

// pack two fp32 -> bf16x2 (lo = a, hi = b)
__device__ __forceinline__ u32 packbf(float a, float b) {
    u32 r;
    asm("cvt.rn.bf16x2.f32 %0, %1, %2;" : "=r"(r) : "f"(b), "f"(a));
    return r;
}

// mask dtype hedge
__device__ __forceinline__ bool mask_at(const void* m, int idx, bool byte_mode) {
    if (byte_mode) return ((const unsigned char*)m)[idx] != 0;
    return ((const unsigned int*)m)[idx] != 0u;
}

// bf16 mma m16n8k16, fp32 accum (baseline PTX; runs on sm_103 tensor pipes)
__device__ __forceinline__ void mma16816(float* c, u32 a0, u32 a1, u32 a2, u32 a3,
                                         u32 b0, u32 b1) {
    asm volatile("mma.sync.aligned.m16n8k16.row.col.f32.bf16.bf16.f32 "
                 "{%0,%1,%2,%3}, {%4,%5,%6,%7}, {%8,%9}, {%0,%1,%2,%3};"
                 : "+f"(c[0]), "+f"(c[1]), "+f"(c[2]), "+f"(c[3])
                 : "r"(a0), "r"(a1), "r"(a2), "r"(a3), "r"(b0), "r"(b1));
}

// split float4 into bf16x2 high/low parts
__device__ __forceinline__ void split4(float4 v, u32& h01, u32& h23,
                                       u32& l01, u32& l23) {
    h01 = packbf(v.x, v.y);
    h23 = packbf(v.z, v.w);
    float hx = __uint_as_float(h01 << 16);
    float hy = __uint_as_float(h01 & 0xffff0000u);
    float hz = __uint_as_float(h23 << 16);
    float hw = __uint_as_float(h23 & 0xffff0000u);
    l01 = packbf(v.x - hx, v.y - hy);
    l23 = packbf(v.z - hz, v.w - hw);
}

// ===========================================================================
// K1: phase A (r12-measured core) + W2 bf16-split tail blocks
// ===========================================================================
__global__ __launch_bounds__(256, 3)
void k1(const float* __restrict__ times,
        const float* __restrict__ features,
        const void*  __restrict__ mask,
        const float* __restrict__ W1,
        const float* __restrict__ b1,
        const float* __restrict__ W2) {
    __shared__ float W1s[CIN * HIDDIM];
    __shared__ float b1s[HIDDIM];
    __shared__ float teu[NWA][CIN][KTAP];
    __shared__ float hb[NWA][KTAP][HIDDIM];

    int tid  = threadIdx.x;

    // ---- tail blocks: pre-split W2 into g_Bh/g_Bl ----
    if (blockIdx.x >= K1BLK) {
        int base = (blockIdx.x - K1BLK) * 8192;
#pragma unroll 4
        for (int i = 0; i < 32; i++) {
            int e = base + i * 256 + tid;          // e < 32768
            int kp = e >> 5, o = e & 31;
            int r0 = 2 * kp;
            int j = r0 >> 5, c = r0 & 31;
            float w0 = W2[j * 1024 + c * 32 + o];
            float w1 = W2[j * 1024 + (c + 1) * 32 + o];
            u32 h = packbf(w0, w1);
            float f0 = __uint_as_float(h << 16);
            float f1 = __uint_as_float(h & 0xffff0000u);
            g_Bh[e] = h;
            g_Bl[e] = packbf(w0 - f0, w1 - f1);
        }
        return;
    }

    int wid  = tid >> 5;
    int lane = tid & 31;

    for (int i = tid; i < CIN * HIDDIM; i += 256) W1s[i] = W1[i];
    if (tid < HIDDIM) b1s[tid] = b1[tid];
    __syncthreads();

    int p = blockIdx.x * NWA + wid;
    int b = p >> 11;
    int t = p & (LEN - 1);

    bool byte_mode = ((const unsigned char*)mask)[1] != 0;
    bool mask_t = mask_at(mask, p, byte_mode);
    float t_here = times[p];

    unsigned vmask = 0;
#pragma unroll
    for (int k = 0; k < KTAP; k++) {
        int idx = t - PADL + k;
        bool dm = mask_t && (idx >= 0);
        if (dm) dm = mask_at(mask, b * LEN + idx, byte_mode);
        if (dm) vmask |= (1u << k);
    }
    bool any = (vmask != 0);
    float fsum = 0.0f;

    if (any) {
        float inv_pos = __expf(-(float)(lane >> 1) * (9.210340371976184f / 16.0f));
        float phase   = (lane & 1) ? 1.5707963267948966f : 0.0f;
        float fk[KTAP];
#pragma unroll
        for (int k = 0; k < KTAP; k++) {
            int idx = t - PADL + k;
            float te = 0.0f;
            fk[k] = 0.0f;
            if ((vmask >> k) & 1) {
                float dt = t_here - times[b * LEN + idx];
                te = __sinf(dt * inv_pos + phase);
                fk[k] = features[(size_t)(b * LEN + idx) * CIN + lane];
            }
            teu[wid][lane][k] = te;
            fsum += fk[k];
        }
        __syncwarp();

        u64 hh[4][2];
#pragma unroll
        for (int k2i = 0; k2i < 4; k2i++) {
            hh[k2i][0] = packdup(b1s[lane]);
            hh[k2i][1] = packdup(b1s[lane + 32]);
        }
#pragma unroll
        for (int i = 0; i < CIN; i++) {
            u64 w0 = packdup(W1s[i * HIDDIM + lane]);
            u64 w1 = packdup(W1s[i * HIDDIM + lane + 32]);
#pragma unroll
            for (int k2i = 0; k2i < 4; k2i++) {
                u64 tp = *(const u64*)&teu[wid][i][2 * k2i];
                FMA2(hh[k2i][0], tp, w0, hh[k2i][0]);
                FMA2(hh[k2i][1], tp, w1, hh[k2i][1]);
            }
        }
#pragma unroll
        for (int k2i = 0; k2i < 4; k2i++) {
            float a0, c0, a1, c1;
            unpack2(hh[k2i][0], a0, c0);
            unpack2(hh[k2i][1], a1, c1);
            hb[wid][2 * k2i][lane]          = fmaxf(a0, 0.0f);
            hb[wid][2 * k2i + 1][lane]      = fmaxf(c0, 0.0f);
            hb[wid][2 * k2i][lane + 32]     = fmaxf(a1, 0.0f);
            hb[wid][2 * k2i + 1][lane + 32] = fmaxf(c1, 0.0f);
        }
        __syncwarp();

#pragma unroll
        for (int half = 0; half < 2; half++) {
            u64 Macc[16];
#pragma unroll
            for (int q = 0; q < 16; q++) Macc[q] = 0ull;
#pragma unroll
            for (int k = 0; k < KTAP; k++) {
                if (!((vmask >> k) & 1)) continue;
                u64 f2 = packdup(fk[k]);
                const ulonglong2* hp2 = (const ulonglong2*)&hb[wid][k][half * 32];
#pragma unroll
                for (int q2 = 0; q2 < 8; q2++) {
                    ulonglong2 hp = hp2[q2];
                    FMA2(Macc[2 * q2],     f2, hp.x, Macc[2 * q2]);
                    FMA2(Macc[2 * q2 + 1], f2, hp.y, Macc[2 * q2 + 1]);
                }
            }
#pragma unroll
            for (int q = 0; q < 16; q++) {
                float m0, m1;
                unpack2(Macc[q], m0, m1);
                int j0 = half * 32 + 2 * q;
                g_Mf[(size_t)p * RDIM + j0 * 32 + lane]       = m0;
                g_Mf[(size_t)p * RDIM + (j0 + 1) * 32 + lane] = m1;
            }
        }
    } else {
#pragma unroll 8
        for (int j = 0; j < HIDDIM; j++)
            g_Mf[(size_t)p * RDIM + j * 32 + lane] = 0.0f;
    }
    g_fsum[p * CIN + lane] = fsum;
}

// ===========================================================================
// K2: bf16-split mma.sync GEMM — C[8192x32] = M @ W2' + epilogue
// ===========================================================================
struct SmemK2 {
    u32 Ah[2][64][68];    // [buf][pos][kp_local] (kp 0-31 = khalf0, 32-63 = khalf1)
    u32 Al[2][64][68];
    u32 Bh[2][64][36];    // [buf][kp_local][o]
    u32 Bl[2][64][36];
    float fs[64][32];
    float ff[64][32];
    float b2s[1024];
    float wsk[1024];
    float bsk[32];
    float ssum[32], ssq[32];
    float Dt[8][16][36];
};

__global__ __launch_bounds__(256)
void k2(const float* __restrict__ features,
        const float* __restrict__ b2,
        const float* __restrict__ Wskip,
        const float* __restrict__ bskip,
        float* __restrict__ out) {
    extern __shared__ char smem_raw[];
    SmemK2* s = (SmemK2*)smem_raw;
    int tid = threadIdx.x, wid = tid >> 5, lane = tid & 31;
    int p0 = blockIdx.x * K2POS;

    for (int e = tid; e < 1024; e += 256) { s->b2s[e] = b2[e]; s->wsk[e] = Wskip[e]; }
    if (tid < 32) { s->bsk[tid] = bskip[tid]; s->ssum[tid] = 0.0f; s->ssq[tid] = 0.0f; }
    for (int e = tid; e < 2048; e += 256) {
        int r = e >> 5, c = e & 31;
        s->fs[r][c] = g_fsum[(p0 + r) * 32 + c];
        s->ff[r][c] = features[(size_t)(p0 + r) * 32 + c];
    }

    // ---- staging helper (macro-ish lambda) ----
    auto stage = [&](int kc, int buf) {
        // A: warp stages 8 rows; lane covers kp = 2*lane, 2*lane+1 (float4)
        int half = lane >> 4;                       // 0: kp<32, 1: kp>=32
        int kflat = half ? (1024 + kc * 64 + 4 * (lane - 16))
                         : (kc * 64 + 4 * lane);
#pragma unroll
        for (int rr = 0; rr < 8; rr++) {
            int pos = wid + rr * 8;
            float4 v = *(const float4*)&g_Mf[(size_t)(p0 + pos) * RDIM + kflat];
            u32 h01, h23, l01, l23;
            split4(v, h01, h23, l01, l23);
            u32* ah = &s->Ah[buf][pos][2 * lane];
            u32* al = &s->Al[buf][pos][2 * lane];
            ah[0] = h01; ah[1] = h23;
            al[0] = l01; al[1] = l23;
        }
        // B: 2048 entries
#pragma unroll
        for (int i = 0; i < 8; i++) {
            int e = i * 256 + tid;
            int kl = e >> 5, o = e & 31;
            int bhalf = kl >> 5;
            int kpg = bhalf * 512 + kc * 32 + (kl & 31);
            s->Bh[buf][kl][o] = g_Bh[kpg * 32 + o];
            s->Bl[buf][kl][o] = g_Bl[kpg * 32 + o];
        }
    };

    stage(0, 0);
    __syncthreads();

    int kh    = wid >> 2;     // K half
    int strip = wid & 3;      // 16-position strip
    int rowA  = strip * 16 + (lane >> 2);

    float c[4][4];
#pragma unroll
    for (int nt = 0; nt < 4; nt++)
#pragma unroll
        for (int q = 0; q < 4; q++) c[nt][q] = 0.0f;

    for (int kc = 0; kc < 16; kc++) {
        int buf = kc & 1;
        if (kc < 15) stage(kc + 1, buf ^ 1);

#pragma unroll
        for (int ks = 0; ks < 4; ks++) {
            int kpb = kh * 32 + ks * 8;
            u32 ah0 = s->Ah[buf][rowA][kpb + (lane & 3)];
            u32 ah1 = s->Ah[buf][rowA + 8][kpb + (lane & 3)];
            u32 ah2 = s->Ah[buf][rowA][kpb + 4 + (lane & 3)];
            u32 ah3 = s->Ah[buf][rowA + 8][kpb + 4 + (lane & 3)];
            u32 al0 = s->Al[buf][rowA][kpb + (lane & 3)];
            u32 al1 = s->Al[buf][rowA + 8][kpb + (lane & 3)];
            u32 al2 = s->Al[buf][rowA][kpb + 4 + (lane & 3)];
            u32 al3 = s->Al[buf][rowA + 8][kpb + 4 + (lane & 3)];
#pragma unroll
            for (int nt = 0; nt < 4; nt++) {
                int n = nt * 8 + (lane >> 2);
                u32 bh0 = s->Bh[buf][kpb + (lane & 3)][n];
                u32 bh1 = s->Bh[buf][kpb + 4 + (lane & 3)][n];
                u32 bl0 = s->Bl[buf][kpb + (lane & 3)][n];
                u32 bl1 = s->Bl[buf][kpb + 4 + (lane & 3)][n];
                mma16816(c[nt], ah0, ah1, ah2, ah3, bh0, bh1);
                mma16816(c[nt], al0, al1, al2, al3, bh0, bh1);
                mma16816(c[nt], ah0, ah1, ah2, ah3, bl0, bl1);
            }
        }
        __syncthreads();
    }

    // ---- write C frags to smem ----
    int cr = lane >> 2, cc = 2 * (lane & 3);
#pragma unroll
    for (int nt = 0; nt < 4; nt++) {
        int n0 = nt * 8;
        s->Dt[wid][cr][n0 + cc]     = c[nt][0];
        s->Dt[wid][cr][n0 + cc + 1] = c[nt][1];
        s->Dt[wid][cr + 8][n0 + cc]     = c[nt][2];
        s->Dt[wid][cr + 8][n0 + cc + 1] = c[nt][3];
    }
    __syncthreads();

    // ---- epilogue: warps 0-3 finalize their strips ----
    if (wid < 4) {
        float osum = 0.0f, osq = 0.0f;
#pragma unroll 2
        for (int i = 0; i < 16; i++) {
            int r = wid * 16 + i;
            float o = s->Dt[wid][i][lane] + s->Dt[wid + 4][i][lane];
            const float4* fs4 = (const float4*)&s->fs[r][0];
            const float4* ff4 = (const float4*)&s->ff[r][0];
#pragma unroll
            for (int q = 0; q < 8; q++) {
                float4 a  = fs4[q];
                float4 cf = ff4[q];
                o += a.x  * s->b2s[(q * 4 + 0) * 32 + lane];
                o += a.y  * s->b2s[(q * 4 + 1) * 32 + lane];
                o += a.z  * s->b2s[(q * 4 + 2) * 32 + lane];
                o += a.w  * s->b2s[(q * 4 + 3) * 32 + lane];
                o += cf.x * s->wsk[(q * 4 + 0) * 32 + lane];
                o += cf.y * s->wsk[(q * 4 + 1) * 32 + lane];
                o += cf.z * s->wsk[(q * 4 + 2) * 32 + lane];
                o += cf.w * s->wsk[(q * 4 + 3) * 32 + lane];
            }
            o += s->bsk[lane];
            out[(size_t)(p0 + r) * 32 + lane] = o;
            osum += o;
            osq  += o * o;
        }
        atomicAdd(&s->ssum[lane], osum);
        atomicAdd(&s->ssq[lane], osq);
    }
    __syncthreads();
    if (tid < 32)       atomicAdd(&g_stats[tid], (double)s->ssum[tid]);
    else if (tid < 64)  atomicAdd(&g_stats[tid], (double)s->ssq[tid - 32]);
}

// ---------------------------------------------------------------------------
// K3: LayerNorm finalize; last block re-zeros g_stats for replay
// ---------------------------------------------------------------------------
__global__ void k3(float* __restrict__ out,
                   const float* __restrict__ gamma,
                   const float* __restrict__ beta) {
    __shared__ float sc[COUT], sb[COUT];
    int tid = threadIdx.x;
    if (tid < COUT) {
        double n = (double)NPOS;
        double mean = g_stats[tid] / n;
        double var  = g_stats[COUT + tid] / n - mean * mean;
        float rstd = rsqrtf((float)var + EPSV);
        float g = gamma[tid] * rstd;
        sc[tid] = g;
        sb[tid] = beta[tid] - g * (float)mean;
    }
    __syncthreads();

    int e4 = blockIdx.x * blockDim.x + tid;
    if (e4 < NPOS * COUT / 4) {
        int o0 = (e4 * 4) & (COUT - 1);
        float4 v = ((const float4*)out)[e4];
        v.x = v.x * sc[o0]     + sb[o0];
        v.y = v.y * sc[o0 + 1] + sb[o0 + 1];
        v.z = v.z * sc[o0 + 2] + sb[o0 + 2];
        v.w = v.w * sc[o0 + 3] + sb[o0 + 3];
        ((float4*)out)[e4] = v;
    }
    __syncthreads();
    if (tid == 0) {
        __threadfence();
        int old = atomicAdd(&g_sync, 1);
        if (old == (int)gridDim.x - 1) {
            for (int i = 0; i < 2 * COUT; i++) g_stats[i] = 0.0;
            __threadfence();
            g_sync = 0;
        }
    }
}

// ---------------------------------------------------------------------------
extern "C" void kernel_launch(void* const* d_in, const int* in_sizes, int n_in,
                              void* d_out, int out_size) {
    const float* times    = (const float*)d_in[0];
    const float* features = (const float*)d_in[1];
    const void*  mask     = d_in[2];
    const float* W1    = (const float*)d_in[3];
    const float* b1    = (const float*)d_in[4];
    const float* W2    = (const float*)d_in[5];
    const float* b2    = (const float*)d_in[6];
    const float* Wskip = (const float*)d_in[7];
    const float* bskip = (const float*)d_in[8];
    const float* gamma = (const float*)d_in[9];
    const float* beta  = (const float*)d_in[10];
    float* out = (float*)d_out;

    cudaFuncSetAttribute(k2, cudaFuncAttributeMaxDynamicSharedMemorySize,
                         (int)sizeof(SmemK2));

    k1<<<K1BLK + 4, 256>>>(times, features, mask, W1, b1, W2);
    k2<<<K2BLK, 256, sizeof(SmemK2)>>>(features, b2, Wskip, bskip, out);
    k3<<<(NPOS * COUT / 4 + 255) / 256, 256>>>(out, gamma, beta);
}

// round 17
// speedup vs baseline: 2.5183x; 1.1740x over previous
#include <cuda_runtime.h>
#include <cuda_bf16.h>
#include <math.h>

#define BS 4
#define LEN 2048
#define CIN 32
#define COUT 32
#define HIDDIM 64
#define KTAP 8
#define PADL 7
#define NPOS (BS * LEN)
#define RDIM 2048
#define EPSV 1e-5f
#define NWA 8
#define K1BLK (NPOS / NWA)        // 1024
#define K2POS 64                   // positions per k2 block
#define K2BLK (NPOS / K2POS)       // 128

typedef unsigned long long u64;
typedef unsigned int u32;

// ---- global scratch ----
// kp'' = q*32 + c  (q = j-pair 0..31, c = channel 0..31); value pair = (M[c][2q], M[c][2q+1])
__device__ u32    g_Ah[(size_t)NPOS * 1024];   // bf16x2 high parts (32MB)
__device__ u32    g_Al[(size_t)NPOS * 1024];   // bf16x2 low parts  (32MB)
__device__ u32    g_Bh[1024 * 32];             // [kp''][o] = (W2[2q][c*32+o], W2[2q+1][c*32+o]) hi
__device__ u32    g_Bl[1024 * 32];
__device__ float  g_fsum[NPOS * CIN];
__device__ double g_stats[2 * COUT];
__device__ int    g_sync;

// ---- packed fp32x2 helpers (k1) ----
#define FMA2(d, a, b, c) \
    asm("fma.rn.f32x2 %0, %1, %2, %3;" : "=l"(d) : "l"(a), "l"(b), "l"(c))
__device__ __forceinline__ u64 packdup(float x) {
    u64 d; asm("mov.b64 %0, {%1, %1};" : "=l"(d) : "f"(x)); return d;
}
__device__ __forceinline__ void unpack2(u64 v, float& x, float& y) {
    asm("mov.b64 {%0, %1}, %2;" : "=f"(x), "=f"(y) : "l"(v));
}
__device__ __forceinline__ u32 packbf(float a, float b) {   // lo = a, hi = b
    u32 r;
    asm("cvt.rn.bf16x2.f32 %0, %1, %2;" : "=r"(r) : "f"(b), "f"(a));
    return r;
}

__device__ __forceinline__ bool mask_at(const void* m, int idx, bool byte_mode) {
    if (byte_mode) return ((const unsigned char*)m)[idx] != 0;
    return ((const unsigned int*)m)[idx] != 0u;
}

__device__ __forceinline__ u32 smem_u32(const void* p) {
    u32 r;
    asm("{ .reg .u64 t; cvta.to.shared.u64 t, %1; cvt.u32.u64 %0, t; }"
        : "=r"(r) : "l"(p));
    return r;
}
__device__ __forceinline__ void cpa16(u32 dst, const void* src) {
    asm volatile("cp.async.ca.shared.global [%0], [%1], 16;" :: "r"(dst), "l"(src));
}
#define CP_COMMIT() asm volatile("cp.async.commit_group;" ::: "memory")
#define CP_WAIT0()  asm volatile("cp.async.wait_group 0;" ::: "memory")

// bf16 mma m16n8k16, fp32 accum
__device__ __forceinline__ void mma16816(float* c, u32 a0, u32 a1, u32 a2, u32 a3,
                                         u32 b0, u32 b1) {
    asm volatile("mma.sync.aligned.m16n8k16.row.col.f32.bf16.bf16.f32 "
                 "{%0,%1,%2,%3}, {%4,%5,%6,%7}, {%8,%9}, {%0,%1,%2,%3};"
                 : "+f"(c[0]), "+f"(c[1]), "+f"(c[2]), "+f"(c[3])
                 : "r"(a0), "r"(a1), "r"(a2), "r"(a3), "r"(b0), "r"(b1));
}

// ===========================================================================
// K1: phase A (r16-passing core) — emits bf16-split A directly + W2 tables
// ===========================================================================
__global__ __launch_bounds__(256, 3)
void k1(const float* __restrict__ times,
        const float* __restrict__ features,
        const void*  __restrict__ mask,
        const float* __restrict__ W1,
        const float* __restrict__ b1,
        const float* __restrict__ W2) {
    __shared__ float W1s[CIN * HIDDIM];
    __shared__ float b1s[HIDDIM];
    __shared__ float teu[NWA][CIN][KTAP];
    __shared__ float hb[NWA][KTAP][HIDDIM];

    int tid  = threadIdx.x;

    // ---- tail blocks: pre-split W2 into g_Bh/g_Bl under kp'' = q*32+c ----
    if (blockIdx.x >= K1BLK) {
        int base = (blockIdx.x - K1BLK) * 8192;
#pragma unroll 4
        for (int i = 0; i < 32; i++) {
            int e = base + i * 256 + tid;          // e < 32768
            int kp = e >> 5, o = e & 31;
            int q = kp >> 5, c = kp & 31;
            float w0 = W2[(2 * q) * 1024 + c * 32 + o];
            float w1 = W2[(2 * q + 1) * 1024 + c * 32 + o];
            u32 h = packbf(w0, w1);
            float f0 = __uint_as_float(h << 16);
            float f1 = __uint_as_float(h & 0xffff0000u);
            g_Bh[e] = h;
            g_Bl[e] = packbf(w0 - f0, w1 - f1);
        }
        return;
    }

    int wid  = tid >> 5;
    int lane = tid & 31;

    for (int i = tid; i < CIN * HIDDIM; i += 256) W1s[i] = W1[i];
    if (tid < HIDDIM) b1s[tid] = b1[tid];
    __syncthreads();

    int p = blockIdx.x * NWA + wid;
    int b = p >> 11;
    int t = p & (LEN - 1);

    bool byte_mode = ((const unsigned char*)mask)[1] != 0;
    bool mask_t = mask_at(mask, p, byte_mode);
    float t_here = times[p];

    unsigned vmask = 0;
#pragma unroll
    for (int k = 0; k < KTAP; k++) {
        int idx = t - PADL + k;
        bool dm = mask_t && (idx >= 0);
        if (dm) dm = mask_at(mask, b * LEN + idx, byte_mode);
        if (dm) vmask |= (1u << k);
    }
    bool any = (vmask != 0);
    float fsum = 0.0f;

    if (any) {
        float inv_pos = __expf(-(float)(lane >> 1) * (9.210340371976184f / 16.0f));
        float phase   = (lane & 1) ? 1.5707963267948966f : 0.0f;
        float fk[KTAP];
#pragma unroll
        for (int k = 0; k < KTAP; k++) {
            int idx = t - PADL + k;
            float te = 0.0f;
            fk[k] = 0.0f;
            if ((vmask >> k) & 1) {
                float dt = t_here - times[b * LEN + idx];
                te = __sinf(dt * inv_pos + phase);
                fk[k] = features[(size_t)(b * LEN + idx) * CIN + lane];
            }
            teu[wid][lane][k] = te;
            fsum += fk[k];
        }
        __syncwarp();

        u64 hh[4][2];
#pragma unroll
        for (int k2i = 0; k2i < 4; k2i++) {
            hh[k2i][0] = packdup(b1s[lane]);
            hh[k2i][1] = packdup(b1s[lane + 32]);
        }
#pragma unroll
        for (int i = 0; i < CIN; i++) {
            u64 w0 = packdup(W1s[i * HIDDIM + lane]);
            u64 w1 = packdup(W1s[i * HIDDIM + lane + 32]);
#pragma unroll
            for (int k2i = 0; k2i < 4; k2i++) {
                u64 tp = *(const u64*)&teu[wid][i][2 * k2i];
                FMA2(hh[k2i][0], tp, w0, hh[k2i][0]);
                FMA2(hh[k2i][1], tp, w1, hh[k2i][1]);
            }
        }
#pragma unroll
        for (int k2i = 0; k2i < 4; k2i++) {
            float a0, c0, a1, c1;
            unpack2(hh[k2i][0], a0, c0);
            unpack2(hh[k2i][1], a1, c1);
            hb[wid][2 * k2i][lane]          = fmaxf(a0, 0.0f);
            hb[wid][2 * k2i + 1][lane]      = fmaxf(c0, 0.0f);
            hb[wid][2 * k2i][lane + 32]     = fmaxf(a1, 0.0f);
            hb[wid][2 * k2i + 1][lane + 32] = fmaxf(c1, 0.0f);
        }
        __syncwarp();

#pragma unroll
        for (int half = 0; half < 2; half++) {
            u64 Macc[16];
#pragma unroll
            for (int q = 0; q < 16; q++) Macc[q] = 0ull;
#pragma unroll
            for (int k = 0; k < KTAP; k++) {
                if (!((vmask >> k) & 1)) continue;
                u64 f2 = packdup(fk[k]);
                const ulonglong2* hp2 = (const ulonglong2*)&hb[wid][k][half * 32];
#pragma unroll
                for (int q2 = 0; q2 < 8; q2++) {
                    ulonglong2 hp = hp2[q2];
                    FMA2(Macc[2 * q2],     f2, hp.x, Macc[2 * q2]);
                    FMA2(Macc[2 * q2 + 1], f2, hp.y, Macc[2 * q2 + 1]);
                }
            }
            // bf16-split store: kp'' = (half*16+q)*32 + lane (coalesced u32)
#pragma unroll
            for (int q = 0; q < 16; q++) {
                float m0, m1;
                unpack2(Macc[q], m0, m1);
                u32 h = packbf(m0, m1);
                float hx = __uint_as_float(h << 16);
                float hy = __uint_as_float(h & 0xffff0000u);
                u32 l = packbf(m0 - hx, m1 - hy);
                int qg = half * 16 + q;
                g_Ah[(size_t)p * 1024 + qg * 32 + lane] = h;
                g_Al[(size_t)p * 1024 + qg * 32 + lane] = l;
            }
        }
    } else {
#pragma unroll 8
        for (int qg = 0; qg < 32; qg++) {
            g_Ah[(size_t)p * 1024 + qg * 32 + lane] = 0u;
            g_Al[(size_t)p * 1024 + qg * 32 + lane] = 0u;
        }
    }
    g_fsum[p * CIN + lane] = fsum;
}

// ===========================================================================
// K2: bf16-split mma.sync GEMM with cp.async double-buffered staging
// ===========================================================================
struct SmemK2 {
    u32 Ah[2][64][68];    // [buf][pos][kp_local 0..63]
    u32 Al[2][64][68];
    u32 Bh[2][64][36];    // [buf][kp_local][o]
    u32 Bl[2][64][36];
    float fs[64][32];
    float ff[64][32];
    float b2s[1024];
    float wsk[1024];
    float bsk[32];
    float ssum[32], ssq[32];
    float Dt[8][16][36];
};

__global__ __launch_bounds__(256)
void k2(const float* __restrict__ features,
        const float* __restrict__ b2,
        const float* __restrict__ Wskip,
        const float* __restrict__ bskip,
        float* __restrict__ out) {
    extern __shared__ char smem_raw[];
    SmemK2* s = (SmemK2*)smem_raw;
    int tid = threadIdx.x, wid = tid >> 5, lane = tid & 31;
    int p0 = blockIdx.x * K2POS;

    for (int e = tid; e < 1024; e += 256) { s->b2s[e] = b2[e]; s->wsk[e] = Wskip[e]; }
    if (tid < 32) { s->bsk[tid] = bskip[tid]; s->ssum[tid] = 0.0f; s->ssq[tid] = 0.0f; }
    for (int e = tid; e < 2048; e += 256) {
        int r = e >> 5, c = e & 31;
        s->fs[r][c] = g_fsum[(p0 + r) * 32 + c];
        s->ff[r][c] = features[(size_t)(p0 + r) * 32 + c];
    }

    // chunk kc covers kp'' in [32kc, 32kc+32) (kp_local 0-31) and
    // [512+32kc, 512+32kc+32) (kp_local 32-63)
    auto stage = [&](int kc, int buf) {
#pragma unroll
        for (int rep = 0; rep < 4; rep++) {
            int u = rep * 256 + tid;          // 0..1023
            int pos = u >> 4, seg = u & 15;
            int kl0 = seg * 4;
            int kpg = ((kl0 >> 5) ? 512 : 0) + kc * 32 + (kl0 & 31);
            size_t srcoff = (size_t)(p0 + pos) * 1024 + kpg;
            cpa16(smem_u32(&s->Ah[buf][pos][kl0]), &g_Ah[srcoff]);
            cpa16(smem_u32(&s->Al[buf][pos][kl0]), &g_Al[srcoff]);
        }
#pragma unroll
        for (int rep = 0; rep < 2; rep++) {
            int u = rep * 256 + tid;          // 0..511
            int kl = u >> 3, oseg = (u & 7) * 4;
            int kpg = (kl >> 5) * 512 + kc * 32 + (kl & 31);
            cpa16(smem_u32(&s->Bh[buf][kl][oseg]), &g_Bh[kpg * 32 + oseg]);
            cpa16(smem_u32(&s->Bl[buf][kl][oseg]), &g_Bl[kpg * 32 + oseg]);
        }
    };

    stage(0, 0);
    CP_COMMIT();
    CP_WAIT0();
    __syncthreads();

    int kh    = wid >> 2;     // K half
    int strip = wid & 3;      // 16-position strip
    int rowA  = strip * 16 + (lane >> 2);

    float c[4][4];
#pragma unroll
    for (int nt = 0; nt < 4; nt++)
#pragma unroll
        for (int q = 0; q < 4; q++) c[nt][q] = 0.0f;

    for (int kc = 0; kc < 16; kc++) {
        int buf = kc & 1;
        if (kc < 15) { stage(kc + 1, buf ^ 1); CP_COMMIT(); }

#pragma unroll
        for (int ks = 0; ks < 4; ks++) {
            int kpb = kh * 32 + ks * 8;
            u32 ah0 = s->Ah[buf][rowA][kpb + (lane & 3)];
            u32 ah1 = s->Ah[buf][rowA + 8][kpb + (lane & 3)];
            u32 ah2 = s->Ah[buf][rowA][kpb + 4 + (lane & 3)];
            u32 ah3 = s->Ah[buf][rowA + 8][kpb + 4 + (lane & 3)];
            u32 al0 = s->Al[buf][rowA][kpb + (lane & 3)];
            u32 al1 = s->Al[buf][rowA + 8][kpb + (lane & 3)];
            u32 al2 = s->Al[buf][rowA][kpb + 4 + (lane & 3)];
            u32 al3 = s->Al[buf][rowA + 8][kpb + 4 + (lane & 3)];
#pragma unroll
            for (int nt = 0; nt < 4; nt++) {
                int n = nt * 8 + (lane >> 2);
                u32 bh0 = s->Bh[buf][kpb + (lane & 3)][n];
                u32 bh1 = s->Bh[buf][kpb + 4 + (lane & 3)][n];
                u32 bl0 = s->Bl[buf][kpb + (lane & 3)][n];
                u32 bl1 = s->Bl[buf][kpb + 4 + (lane & 3)][n];
                mma16816(c[nt], ah0, ah1, ah2, ah3, bh0, bh1);
                mma16816(c[nt], al0, al1, al2, al3, bh0, bh1);
                mma16816(c[nt], ah0, ah1, ah2, ah3, bl0, bl1);
            }
        }
        if (kc < 15) CP_WAIT0();
        __syncthreads();
    }

    // ---- write C frags to smem ----
    int cr = lane >> 2, cc = 2 * (lane & 3);
#pragma unroll
    for (int nt = 0; nt < 4; nt++) {
        int n0 = nt * 8;
        s->Dt[wid][cr][n0 + cc]         = c[nt][0];
        s->Dt[wid][cr][n0 + cc + 1]     = c[nt][1];
        s->Dt[wid][cr + 8][n0 + cc]     = c[nt][2];
        s->Dt[wid][cr + 8][n0 + cc + 1] = c[nt][3];
    }
    __syncthreads();

    // ---- epilogue: warps 0-3 finalize their strips ----
    if (wid < 4) {
        float osum = 0.0f, osq = 0.0f;
#pragma unroll 2
        for (int i = 0; i < 16; i++) {
            int r = wid * 16 + i;
            float o = s->Dt[wid][i][lane] + s->Dt[wid + 4][i][lane];
            const float4* fs4 = (const float4*)&s->fs[r][0];
            const float4* ff4 = (const float4*)&s->ff[r][0];
#pragma unroll
            for (int q = 0; q < 8; q++) {
                float4 a  = fs4[q];
                float4 cf = ff4[q];
                o += a.x  * s->b2s[(q * 4 + 0) * 32 + lane];
                o += a.y  * s->b2s[(q * 4 + 1) * 32 + lane];
                o += a.z  * s->b2s[(q * 4 + 2) * 32 + lane];
                o += a.w  * s->b2s[(q * 4 + 3) * 32 + lane];
                o += cf.x * s->wsk[(q * 4 + 0) * 32 + lane];
                o += cf.y * s->wsk[(q * 4 + 1) * 32 + lane];
                o += cf.z * s->wsk[(q * 4 + 2) * 32 + lane];
                o += cf.w * s->wsk[(q * 4 + 3) * 32 + lane];
            }
            o += s->bsk[lane];
            out[(size_t)(p0 + r) * 32 + lane] = o;
            osum += o;
            osq  += o * o;
        }
        atomicAdd(&s->ssum[lane], osum);
        atomicAdd(&s->ssq[lane], osq);
    }
    __syncthreads();
    if (tid < 32)       atomicAdd(&g_stats[tid], (double)s->ssum[tid]);
    else if (tid < 64)  atomicAdd(&g_stats[tid], (double)s->ssq[tid - 32]);
}

// ---------------------------------------------------------------------------
// K3: LayerNorm finalize; last block re-zeros g_stats for replay
// ---------------------------------------------------------------------------
__global__ void k3(float* __restrict__ out,
                   const float* __restrict__ gamma,
                   const float* __restrict__ beta) {
    __shared__ float sc[COUT], sb[COUT];
    int tid = threadIdx.x;
    if (tid < COUT) {
        double n = (double)NPOS;
        double mean = g_stats[tid] / n;
        double var  = g_stats[COUT + tid] / n - mean * mean;
        float rstd = rsqrtf((float)var + EPSV);
        float g = gamma[tid] * rstd;
        sc[tid] = g;
        sb[tid] = beta[tid] - g * (float)mean;
    }
    __syncthreads();

    int e4 = blockIdx.x * blockDim.x + tid;
    if (e4 < NPOS * COUT / 4) {
        int o0 = (e4 * 4) & (COUT - 1);
        float4 v = ((const float4*)out)[e4];
        v.x = v.x * sc[o0]     + sb[o0];
        v.y = v.y * sc[o0 + 1] + sb[o0 + 1];
        v.z = v.z * sc[o0 + 2] + sb[o0 + 2];
        v.w = v.w * sc[o0 + 3] + sb[o0 + 3];
        ((float4*)out)[e4] = v;
    }
    __syncthreads();
    if (tid == 0) {
        __threadfence();
        int old = atomicAdd(&g_sync, 1);
        if (old == (int)gridDim.x - 1) {
            for (int i = 0; i < 2 * COUT; i++) g_stats[i] = 0.0;
            __threadfence();
            g_sync = 0;
        }
    }
}

// ---------------------------------------------------------------------------
extern "C" void kernel_launch(void* const* d_in, const int* in_sizes, int n_in,
                              void* d_out, int out_size) {
    const float* times    = (const float*)d_in[0];
    const float* features = (const float*)d_in[1];
    const void*  mask     = d_in[2];
    const float* W1    = (const float*)d_in[3];
    const float* b1    = (const float*)d_in[4];
    const float* W2    = (const float*)d_in[5];
    const float* b2    = (const float*)d_in[6];
    const float* Wskip = (const float*)d_in[7];
    const float* bskip = (const float*)d_in[8];
    const float* gamma = (const float*)d_in[9];
    const float* beta  = (const float*)d_in[10];
    float* out = (float*)d_out;

    cudaFuncSetAttribute(k2, cudaFuncAttributeMaxDynamicSharedMemorySize,
                         (int)sizeof(SmemK2));

    k1<<<K1BLK + 4, 256>>>(times, features, mask, W1, b1, W2);
    k2<<<K2BLK, 256, sizeof(SmemK2)>>>(features, b2, Wskip, bskip, out);
    k3<<<(NPOS * COUT / 4 + 255) / 256, 256>>>(out, gamma, beta);
}